// round 3
// baseline (speedup 1.0000x reference)
#include <cuda_runtime.h>

#define IH 256
#define IW 256
#define OH 254
#define OW 254
#define TW 32
#define TH 16
#define HTW (TW + 2)   // 34
#define HTH (TH + 2)   // 18
#define NPIX (HTW * HTH) // 612

// Closed-form uniform cubic B-spline KAN conv.
// grid spacing h = 0.4, lo = -1. t = (x+1)/h, i = floor(t) in [0,4] for x in [-1,1].
// spline contribution for position p: cubic in f = t - i with coefs from sw[p][i..i+3].

__global__ __launch_bounds__(256, 2)
void kan_conv_kernel(const float* __restrict__ x,
                     const float* __restrict__ bw,
                     const float* __restrict__ sw,
                     float* __restrict__ out)
{
    __shared__ float4 scoef[5 * 9];        // [interval i][position p] -> (A,B,C,D)
    __shared__ float  swb[9];
    __shared__ float  sc[NPIX * 9];        // per-pixel contributions c_p

    const int tid = threadIdx.x;

    // ---- build Horner coefficient table (A + B f + C f^2 + D f^3) ----
    if (tid < 45) {
        int i = tid / 9;       // interval 0..4
        int p = tid - i * 9;   // kernel position 0..8
        float s0 = sw[p * 8 + i + 0];
        float s1 = sw[p * 8 + i + 1];
        float s2 = sw[p * 8 + i + 2];
        float s3 = sw[p * 8 + i + 3];
        float A = (s0 + 4.0f * s1 + s2) * (1.0f / 6.0f);
        float B = (s2 - s0) * 0.5f;
        float C = (s0 - 2.0f * s1 + s2) * 0.5f;
        float D = (-s0 + 3.0f * s1 - 3.0f * s2 + s3) * (1.0f / 6.0f);
        scoef[tid] = make_float4(A, B, C, D);
    }
    if (tid < 9) swb[tid] = bw[tid];
    __syncthreads();

    float wbr[9];
#pragma unroll
    for (int p = 0; p < 9; p++) wbr[p] = swb[p];

    const int bz  = blockIdx.z;
    const int oh0 = blockIdx.y * TH;
    const int ow0 = blockIdx.x * TW;
    const float* xb = x + bz * (IH * IW);

    // ---- phase 1: per input pixel, compute 9 contribution values ----
    for (int idx = tid; idx < NPIX; idx += 256) {
        int iy = idx / HTW;
        int ix = idx - iy * HTW;
        int gy = oh0 + iy;
        int gx = ow0 + ix;
        // clamp for safety: clamped pixels only feed out-of-range outputs
        if (gy > IH - 1) gy = IH - 1;
        if (gx > IW - 1) gx = IW - 1;
        float v = xb[gy * IW + gx];

        float t = fmaf(v, 2.5f, 2.5f);       // (v + 1) / 0.4
        int   i = (int)t;
        if (i > 4) i = 4;
        if (i < 0) i = 0;
        float f = t - (float)i;
        float f2 = f * f;

        // silu(v) = v * sigmoid(v)
        float sil = __fdividef(v, 1.0f + __expf(-v));

        const float4* cf = &scoef[i * 9];
        float* dst = &sc[idx * 9];
#pragma unroll
        for (int p = 0; p < 9; p++) {
            float4 co = cf[p];
            float poly = co.x + f * co.y + f2 * (co.z + f * co.w);
            dst[p] = fmaf(sil, wbr[p], poly);
        }
    }
    __syncthreads();

    // ---- phase 2: stencil gather, 2 output rows per thread ----
    const int lx = tid & 31;
    const int ty = tid >> 5;  // 0..7
    const int ow = ow0 + lx;

#pragma unroll
    for (int r = 0; r < 2; r++) {
        int ly = ty * 2 + r;
        int oh = oh0 + ly;
        if (oh < OH && ow < OW) {
            float acc = 0.0f;
#pragma unroll
            for (int a = 0; a < 3; a++) {
#pragma unroll
                for (int b = 0; b < 3; b++) {
                    acc += sc[((ly + a) * HTW + (lx + b)) * 9 + (a * 3 + b)];
                }
            }
            out[bz * (OH * OW) + oh * OW + ow] = acc;
        }
    }
}

extern "C" void kernel_launch(void* const* d_in, const int* in_sizes, int n_in,
                              void* d_out, int out_size)
{
    const float* x  = (const float*)d_in[0];
    const float* bw = (const float*)d_in[1];
    const float* sw = (const float*)d_in[2];
    float* out = (float*)d_out;

    dim3 block(256);
    dim3 grid((OW + TW - 1) / TW, (OH + TH - 1) / TH, 32);
    kan_conv_kernel<<<grid, block>>>(x, bw, sw, out);
}